// round 6
// baseline (speedup 1.0000x reference)
#include <cuda_runtime.h>

// AllZeroDigitalFilter, scalar-FFMA density build.
//   out[b, n*P+p] = y0 + (p/P)*y1 ; y0 = x*h0, y1 = x*(h1-h0)
// RR=8 outputs/thread, K-split x2 (two 80-thread teams x 128 taps),
// 16-reg sliding window with period-2 role swap (zero shift-MOVs),
// {h0,d}-interleaved coefficients, double-buffered coeff quads.

#define TAPS 256
#define HALF 128
#define MM   255
#define PP   80
#define SEG  8
#define OUTB (SEG * PP)            // 640
#define RR   8
#define TEAM (OUTB / RR)           // 80 threads per team
#define NTHREADS (2 * TEAM)        // 160
#define NB 800
#define BB 8
#define TT (NB * PP)
#define CPS 258                    // float2 stride per segment
#define SPS 20                     // spart stride (floats)

#define TAP8(hc, dc, v0,v1,v2,v3,v4,v5,v6,v7) \
    A0 += (v0)*(hc); B0 += (v0)*(dc); A1 += (v1)*(hc); B1 += (v1)*(dc); \
    A2 += (v2)*(hc); B2 += (v2)*(dc); A3 += (v3)*(hc); B3 += (v3)*(dc); \
    A4 += (v4)*(hc); B4 += (v4)*(dc); A5 += (v5)*(hc); B5 += (v5)*(dc); \
    A6 += (v6)*(hc); B6 += (v6)*(dc); A7 += (v7)*(hc); B7 += (v7)*(dc);

// One 8-tap iteration. Window invariant: W[i] = wb[248 - 8*KK + i];
// L holds W0..7, H holds W8..15. Tap u uses W[7-u+r] for outputs r=0..7.
// Fresh loads for the next iteration land in H exactly when those regs die.
// QN* quads are next-iteration coefficients (double buffer).
#define PHASE(L, H, QA0, QA1, QA2, QA3, QB0, QB1, QB2, QB3, KK) { \
    TAP8((QA0).x, (QA0).y, L##7,H##0,H##1,H##2,H##3,H##4,H##5,H##6) \
    TAP8((QA0).z, (QA0).w, L##6,L##7,H##0,H##1,H##2,H##3,H##4,H##5) \
    TAP8((QA1).x, (QA1).y, L##5,L##6,L##7,H##0,H##1,H##2,H##3,H##4) \
    { float4 nf = *(const float4*)(wb + 244 - 8*(KK)); \
      H##4 = nf.x; H##5 = nf.y; H##6 = nf.z; H##7 = nf.w; } \
    TAP8((QA1).z, (QA1).w, L##4,L##5,L##6,L##7,H##0,H##1,H##2,H##3) \
    QB0 = *(const float4*)(cp2 + 8*((KK)+1)); \
    QB1 = *(const float4*)(cp2 + 8*((KK)+1) + 2); \
    QB2 = *(const float4*)(cp2 + 8*((KK)+1) + 4); \
    QB3 = *(const float4*)(cp2 + 8*((KK)+1) + 6); \
    TAP8((QA2).x, (QA2).y, L##3,L##4,L##5,L##6,L##7,H##0,H##1,H##2) \
    TAP8((QA2).z, (QA2).w, L##2,L##3,L##4,L##5,L##6,L##7,H##0,H##1) \
    TAP8((QA3).x, (QA3).y, L##1,L##2,L##3,L##4,L##5,L##6,L##7,H##0) \
    { float4 nf = *(const float4*)(wb + 240 - 8*(KK)); \
      H##0 = nf.x; H##1 = nf.y; H##2 = nf.z; H##3 = nf.w; } \
    TAP8((QA3).z, (QA3).w, L##0,L##1,L##2,L##3,L##4,L##5,L##6,L##7) \
}

__global__ __launch_bounds__(NTHREADS, 5)
void azdf_kernel(const float* __restrict__ x,
                 const float* __restrict__ h,
                 float* __restrict__ out)
{
    __shared__ float2 scp[SEG * CPS + 8];              // {h0,d} pairs (+pad for dead prefetch)
    __shared__ __align__(16) float sx[8 + TAPS + OUTB];
    __shared__ float spart[TEAM * SPS];

    const int tid = threadIdx.x;
    const int b   = blockIdx.y;
    const int n0  = blockIdx.x * SEG;

    // ---- stage filters as interleaved {h0, d}
    {
        const float* hb = h + (size_t)b * NB * TAPS;
        for (int idx = tid; idx < SEG * TAPS; idx += NTHREADS) {
            int s = idx >> 8, k = idx & 255;
            int n  = n0 + s;
            int nn = (n + 1 < NB) ? (n + 1) : (NB - 1);
            float a = hb[(size_t)n  * TAPS + k];
            float c = hb[(size_t)nn * TAPS + k];
            scp[s * CPS + k] = make_float2(a, c - a);
        }
    }
    // ---- stage x window (8-float front pad; OOB -> 0)
    {
        const float* xb = x + (size_t)b * TT;
        const int gbase = n0 * PP - MM;
        for (int j = tid; j < TAPS + OUTB; j += NTHREADS) {
            int g = gbase + j;
            sx[8 + j] = (g >= 0 && g < TT) ? xb[g] : 0.0f;
        }
        if (tid < 8) sx[tid] = 0.0f;
    }
    __syncthreads();

    const int lane = (tid < TEAM) ? tid : (tid - TEAM);
    const int team = (tid < TEAM) ? 0 : 1;
    const int koff = team * HALF;
    const int pout = lane * RR;
    const int s    = lane / (PP / RR);                 // lane/10
    const float2* cp2 = scp + s * CPS + koff;
    const float*  wb  = sx + 8 + pout - koff;

    float A0=0,A1=0,A2=0,A3=0,A4=0,A5=0,A6=0,A7=0;
    float B0=0,B1=0,B2=0,B3=0,B4=0,B5=0,B6=0,B7=0;

    float a0,a1,a2,a3,a4,a5,a6,a7, b0,b1,b2,b3,b4,b5,b6,b7;
    {
        float4 t0 = *(const float4*)(wb + 248);
        float4 t1 = *(const float4*)(wb + 252);
        float4 t2 = *(const float4*)(wb + 256);
        float4 t3 = *(const float4*)(wb + 260);
        a0=t0.x; a1=t0.y; a2=t0.z; a3=t0.w;
        a4=t1.x; a5=t1.y; a6=t1.z; a7=t1.w;
        b0=t2.x; b1=t2.y; b2=t2.z; b3=t2.w;
        b4=t3.x; b5=t3.y; b6=t3.z; b7=t3.w;
    }
    float4 qa0 = *(const float4*)(cp2 + 0);
    float4 qa1 = *(const float4*)(cp2 + 2);
    float4 qa2 = *(const float4*)(cp2 + 4);
    float4 qa3 = *(const float4*)(cp2 + 6);
    float4 qb0, qb1, qb2, qb3;

    #pragma unroll 1
    for (int kk = 0; kk < HALF / 8; kk += 2) {
        PHASE(a, b, qa0, qa1, qa2, qa3, qb0, qb1, qb2, qb3, kk)
        PHASE(b, a, qb0, qb1, qb2, qb3, qa0, qa1, qa2, qa3, kk + 1)
    }

    if (team == 1) {
        float* sp = spart + lane * SPS;
        ((float4*)sp)[0] = make_float4(A0, A1, A2, A3);
        ((float4*)sp)[1] = make_float4(A4, A5, A6, A7);
        ((float4*)sp)[2] = make_float4(B0, B1, B2, B3);
        ((float4*)sp)[3] = make_float4(B4, B5, B6, B7);
    }
    __syncthreads();
    if (team == 0) {
        const float* sp = spart + lane * SPS;
        float4 pa0 = ((const float4*)sp)[0];
        float4 pa1 = ((const float4*)sp)[1];
        float4 pb0 = ((const float4*)sp)[2];
        float4 pb1 = ((const float4*)sp)[3];
        A0 += pa0.x; A1 += pa0.y; A2 += pa0.z; A3 += pa0.w;
        A4 += pa1.x; A5 += pa1.y; A6 += pa1.z; A7 += pa1.w;
        B0 += pb0.x; B1 += pb0.y; B2 += pb0.z; B3 += pb0.w;
        B4 += pb1.x; B5 += pb1.y; B6 += pb1.z; B7 += pb1.w;

        const float p   = (float)(pout - s * PP);
        const float inv = 1.0f / (float)PP;
        float4 o0, o1;
        o0.x = A0 + (p + 0.0f) * inv * B0;
        o0.y = A1 + (p + 1.0f) * inv * B1;
        o0.z = A2 + (p + 2.0f) * inv * B2;
        o0.w = A3 + (p + 3.0f) * inv * B3;
        o1.x = A4 + (p + 4.0f) * inv * B4;
        o1.y = A5 + (p + 5.0f) * inv * B5;
        o1.z = A6 + (p + 6.0f) * inv * B6;
        o1.w = A7 + (p + 7.0f) * inv * B7;
        float4* op = (float4*)(out + (size_t)b * TT + n0 * PP + pout);
        op[0] = o0; op[1] = o1;
    }
}

extern "C" void kernel_launch(void* const* d_in, const int* in_sizes, int n_in,
                              void* d_out, int out_size)
{
    const float* x = (const float*)d_in[0];
    const float* h = (const float*)d_in[1];
    float* out = (float*)d_out;
    (void)in_sizes; (void)n_in; (void)out_size;

    dim3 grid(NB / SEG, BB);   // 100 x 8
    azdf_kernel<<<grid, NTHREADS>>>(x, h, out);
}